// round 16
// baseline (speedup 1.0000x reference)
#include <cuda_runtime.h>
#include <cuda_fp16.h>
#include <cstdint>

// ---------------------------------------------------------------------------
// SimpleMaxViTBlock: LN1 -> per-token head-mixing attention -> +res
//                    -> LN2 -> [FFN1+FFN2 fused, h in smem] -> +res
// GEMMs: mma.sync m16n8k16 fp16, fp32 accum, ldmatrix, cp.async.
// R16: R15 with the fused-FFN A-tile loader fixed (was loading 512 of 2048
// 16B chunks -> garbage in K-chunks 2..7 of phase 1).
// ---------------------------------------------------------------------------

constexpr int TOKENS = 65536;
constexpr int DIM    = 256;
constexpr int HEADS  = 8;
constexpr int HD     = 32;
constexpr int FFNDIM = 1024;

// Scratch (device globals: allocation-free rule)
__device__ __half g_xn  [ (size_t)TOKENS * DIM    ];
__device__ __half g_qkv [ (size_t)TOKENS * 3*DIM  ];
__device__ __half g_attn[ (size_t)TOKENS * DIM    ];
__device__ __half g_y   [ (size_t)TOKENS * DIM    ];   // fp16 residual
__device__ __half g_w   [ 786432 ];   // fp16-rounded weights

constexpr int W_QKV  = 0;
constexpr int W_PROJ = 196608;
constexpr int W_FFN1 = 262144;
constexpr int W_FFN2 = 524288;

// ===================== helpers ==============================================
__device__ __forceinline__ uint32_t smem_u32(const void* p) {
    uint32_t a;
    asm("{ .reg .u64 t; cvta.to.shared.u64 t, %1; cvt.u32.u64 %0, t; }"
        : "=r"(a) : "l"(p));
    return a;
}
__device__ __forceinline__ void cp_async16(uint32_t saddr, const void* gaddr) {
    asm volatile("cp.async.cg.shared.global [%0], [%1], 16;"
                 :: "r"(saddr), "l"(gaddr) : "memory");
}
__device__ __forceinline__ void cp_commit() {
    asm volatile("cp.async.commit_group;" ::: "memory");
}
template<int N>
__device__ __forceinline__ void cp_wait() {
    asm volatile("cp.async.wait_group %0;" :: "n"(N) : "memory");
}
__device__ __forceinline__ void ldm_x4(uint32_t& r0, uint32_t& r1,
                                       uint32_t& r2, uint32_t& r3, uint32_t addr) {
    asm volatile("ldmatrix.sync.aligned.m8n8.x4.shared.b16 {%0,%1,%2,%3}, [%4];"
                 : "=r"(r0), "=r"(r1), "=r"(r2), "=r"(r3) : "r"(addr));
}
__device__ __forceinline__ void mma_f16(
    float& d0, float& d1, float& d2, float& d3,
    uint32_t a0, uint32_t a1, uint32_t a2, uint32_t a3,
    uint32_t b0, uint32_t b1)
{
    asm volatile(
        "mma.sync.aligned.m16n8k16.row.col.f32.f16.f16.f32 "
        "{%0,%1,%2,%3}, {%4,%5,%6,%7}, {%8,%9}, {%0,%1,%2,%3};"
        : "+f"(d0), "+f"(d1), "+f"(d2), "+f"(d3)
        : "r"(a0), "r"(a1), "r"(a2), "r"(a3), "r"(b0), "r"(b1));
}

// ===================== fp16 mma.sync GEMM (R8 config) =======================
// MODE: 0 = bias, 1 = bias+relu, 2 = bias+residual(ResT)
constexpr int TILE  = 128;
constexpr int BK    = 32;
constexpr int LDU   = 20;              // u32 per smem row (= 40 halves, 80B)
constexpr int SLABU = TILE * LDU;      // 2560 u32 per stage per matrix

template<int MODE, typename ResT, typename OutT>
__global__ void __launch_bounds__(128, 2) mma_gemm(
    const __half* __restrict__ A, const __half* __restrict__ B,
    const float* __restrict__ bias, const ResT* __restrict__ res,
    OutT* __restrict__ C, int K, int N)
{
    __shared__ __align__(16) uint32_t sm[4 * SLABU];   // 40960 B
    const uint32_t As_u = smem_u32(sm);
    const uint32_t Bs_u = As_u + 2 * SLABU * 4;

    const int tid  = threadIdx.x;
    const int wid  = tid >> 5;
    const int lane = tid & 31;
    const int gid  = lane >> 2;
    const int tg   = lane & 3;

    const int bm = blockIdx.y * TILE;
    const int bn = blockIdx.x * TILE;
    const int m_off = (wid >> 1) * 64;
    const int n_off = (wid & 1) * 64;

    const int lrow8 = lane & 7;
    const int a_row = (lrow8 + ((lane >> 3) & 1) * 8);
    const int a_kof = (lane >> 4) * 4;
    const int b_row = (lrow8 + ((lane >> 4) & 1) * 8);
    const int b_kof = ((lane >> 3) & 1) * 4;

    const int crow = tid >> 2;
    const int cc4  = (tid & 3) * 4;

    float d[4][8][4];
#pragma unroll
    for (int mt = 0; mt < 4; mt++)
#pragma unroll
        for (int nt = 0; nt < 8; nt++)
#pragma unroll
            for (int j = 0; j < 4; j++) d[mt][nt][j] = 0.0f;

    const int C_CHUNKS = K / BK;

    {
#pragma unroll
        for (int it = 0; it < 4; it++) {
            int row = crow + it * 32;
            cp_async16(As_u + (uint32_t)(row * LDU + cc4) * 4,
                       A + (size_t)(bm + row) * K + cc4 * 2);
            cp_async16(Bs_u + (uint32_t)(row * LDU + cc4) * 4,
                       B + (size_t)(bn + row) * K + cc4 * 2);
        }
        cp_commit();
    }

    for (int c = 0; c < C_CHUNKS; c++) {
        const int buf = c & 1;
        if (c + 1 < C_CHUNKS) {
            const int nb  = (c + 1) & 1;
            const int k0g = (c + 1) * BK;
#pragma unroll
            for (int it = 0; it < 4; it++) {
                int row = crow + it * 32;
                cp_async16(As_u + (uint32_t)((nb * SLABU + row * LDU + cc4) * 4),
                           A + (size_t)(bm + row) * K + k0g + cc4 * 2);
                cp_async16(Bs_u + (uint32_t)((nb * SLABU + row * LDU + cc4) * 4),
                           B + (size_t)(bn + row) * K + k0g + cc4 * 2);
            }
            cp_commit();
            cp_wait<1>();
        } else {
            cp_wait<0>();
        }
        __syncthreads();

        const uint32_t Ab = As_u + (uint32_t)(buf * SLABU) * 4;
        const uint32_t Bb = Bs_u + (uint32_t)(buf * SLABU) * 4;

#pragma unroll
        for (int ks = 0; ks < 2; ks++) {
            const int ko = ks * 8;
            uint32_t a[4][4];
#pragma unroll
            for (int mt = 0; mt < 4; mt++) {
                uint32_t addr = Ab + (uint32_t)(
                    (m_off + mt * 16 + a_row) * LDU + ko + a_kof) * 4;
                ldm_x4(a[mt][0], a[mt][1], a[mt][2], a[mt][3], addr);
            }
            uint32_t b[8][2];
#pragma unroll
            for (int np = 0; np < 4; np++) {
                uint32_t addr = Bb + (uint32_t)(
                    (n_off + np * 16 + b_row) * LDU + ko + b_kof) * 4;
                ldm_x4(b[2*np][0], b[2*np][1], b[2*np+1][0], b[2*np+1][1], addr);
            }
#pragma unroll
            for (int mt = 0; mt < 4; mt++)
#pragma unroll
                for (int nt = 0; nt < 8; nt++)
                    mma_f16(d[mt][nt][0], d[mt][nt][1], d[mt][nt][2], d[mt][nt][3],
                            a[mt][0], a[mt][1], a[mt][2], a[mt][3],
                            b[nt][0], b[nt][1]);
        }
        __syncthreads();
    }

#pragma unroll
    for (int nt = 0; nt < 8; nt++) {
        const int n = bn + n_off + nt * 8 + 2 * tg;
        const float2 bv = *(const float2*)&bias[n];
#pragma unroll
        for (int mt = 0; mt < 4; mt++) {
            const int m0 = bm + m_off + mt * 16 + gid;
#pragma unroll
            for (int half_i = 0; half_i < 2; half_i++) {
                const int m = m0 + half_i * 8;
                float vx = d[mt][nt][half_i * 2 + 0] + bv.x;
                float vy = d[mt][nt][half_i * 2 + 1] + bv.y;
                if (MODE == 1) { vx = fmaxf(vx, 0.f); vy = fmaxf(vy, 0.f); }
                if (MODE == 2) {
                    if constexpr (sizeof(ResT) == 4) {
                        const float2 r = *(const float2*)&res[(size_t)m * N + n];
                        vx += r.x; vy += r.y;
                    } else {
                        const __half2 r = *(const __half2*)&res[(size_t)m * N + n];
                        float2 rf = __half22float2(r);
                        vx += rf.x; vy += rf.y;
                    }
                }
                if constexpr (sizeof(OutT) == 4) {
                    float2 v; v.x = vx; v.y = vy;
                    *(float2*)&((float*)C)[(size_t)m * N + n] = v;
                } else {
                    *(__half2*)&((__half*)C)[(size_t)m * N + n] =
                        __floats2half2_rn(vx, vy);
                }
            }
        }
    }
}

// ===================== fused FFN: out = relu(xn@W1^T+b1)@W2^T + b2 + y ======
// CTA = 64 tokens, 256 threads (8 warps). h (64x1024 fp16) resident in smem.
constexpr int FH_U = 516;     // u32 per h row (1032 halves; 2064B = 16 mod 128)
constexpr int FA_U = 132;     // u32 per A row  (264 halves;  528B = 16 mod 128)
constexpr int FB_STG = 256 * LDU;   // 5120 u32 per B stage
constexpr int FUSED_SMEM = (64 * FH_U + 64 * FA_U + 2 * FB_STG) * 4;  // 206848

__global__ void __launch_bounds__(256, 1) fused_ffn(
    const __half* __restrict__ xn, const __half* __restrict__ W1,
    const float* __restrict__ b1, const __half* __restrict__ W2,
    const float* __restrict__ b2, const __half* __restrict__ y,
    float* __restrict__ out)
{
    extern __shared__ uint32_t smf[];
    uint32_t* Hp = smf;                          // [64][516]
    const uint32_t H_u = smem_u32(smf);
    const uint32_t A_u = H_u + 64 * FH_U * 4;    // [64][132]
    const uint32_t B_u = A_u + 64 * FA_U * 4;    // [2][256][20]

    const int tid  = threadIdx.x;
    const int wid  = tid >> 5;
    const int lane = tid & 31;
    const int gid  = lane >> 2;
    const int tg   = lane & 3;
    const int bm   = blockIdx.x * 64;

    const int lrow8 = lane & 7;
    const int a_row = (lrow8 + ((lane >> 3) & 1) * 8);
    const int a_kof = (lane >> 4) * 4;
    const int b_row = (lrow8 + ((lane >> 4) & 1) * 8);
    const int b_kof = ((lane >> 3) & 1) * 4;

    // ---- load A (xn tile 64x256): 2048 16B transfers = 8 it x 256 thr ----
    {
#pragma unroll
        for (int it = 0; it < 8; it++) {
            int fi  = tid + it * 256;     // 0..2047
            int row = fi >> 5;            // 0..63
            int c32 = fi & 31;            // 16B chunk within 256-half row
            cp_async16(A_u + (uint32_t)(row * FA_U + c32 * 4) * 4,
                       xn + (size_t)(bm + row) * DIM + c32 * 8);
        }
        cp_commit();
    }

    // ================= phase 1: h = relu(xn @ W1^T + b1) ==================
    const int m1 = (wid >> 2) * 32;     // 0,32
    const int n1 = (wid & 3) * 32;      // 0,32,64,96

    auto issueB1 = [&](int c, int s) {
        const int nc = c >> 3, kc = c & 7;
#pragma unroll
        for (int it = 0; it < 2; it++) {
            int fi  = tid + it * 256;
            int row = fi >> 2;
            int c4  = (fi & 3) * 4;
            cp_async16(B_u + (uint32_t)(s * FB_STG + row * LDU + c4) * 4,
                       W1 + (size_t)(nc * 128 + row) * DIM + kc * 32 + c4 * 2);
        }
        cp_commit();
    };

    issueB1(0, 0);
    float d1[2][4][4];

    for (int c = 0; c < 64; c++) {
        const int nc = c >> 3, kc = c & 7;
        if (kc == 0) {
#pragma unroll
            for (int mt = 0; mt < 2; mt++)
#pragma unroll
                for (int nt = 0; nt < 4; nt++)
#pragma unroll
                    for (int j = 0; j < 4; j++) d1[mt][nt][j] = 0.0f;
        }
        if (c + 1 < 64) { issueB1(c + 1, (c + 1) & 1); cp_wait<1>(); }
        else            { cp_wait<0>(); }
        __syncthreads();

        const uint32_t Bb = B_u + (uint32_t)((c & 1) * FB_STG) * 4;

#pragma unroll
        for (int ks = 0; ks < 2; ks++) {
            const int ko = kc * 16 + ks * 8;
            uint32_t a[2][4];
#pragma unroll
            for (int mt = 0; mt < 2; mt++) {
                uint32_t addr = A_u + (uint32_t)(
                    (m1 + mt * 16 + a_row) * FA_U + ko + a_kof) * 4;
                ldm_x4(a[mt][0], a[mt][1], a[mt][2], a[mt][3], addr);
            }
            uint32_t b[4][2];
#pragma unroll
            for (int np = 0; np < 2; np++) {
                uint32_t addr = Bb + (uint32_t)(
                    (n1 + np * 16 + b_row) * LDU + ks * 8 + b_kof) * 4;
                ldm_x4(b[2*np][0], b[2*np][1], b[2*np+1][0], b[2*np+1][1], addr);
            }
#pragma unroll
            for (int mt = 0; mt < 2; mt++)
#pragma unroll
                for (int nt = 0; nt < 4; nt++)
                    mma_f16(d1[mt][nt][0], d1[mt][nt][1], d1[mt][nt][2], d1[mt][nt][3],
                            a[mt][0], a[mt][1], a[mt][2], a[mt][3],
                            b[nt][0], b[nt][1]);
        }

        if (kc == 7) {
            // epilogue: relu(+bias) -> h smem (fp16)
#pragma unroll
            for (int nt = 0; nt < 4; nt++) {
                const int gn = nc * 128 + n1 + nt * 8 + 2 * tg;
                const float2 bv = *(const float2*)&b1[gn];
#pragma unroll
                for (int mt = 0; mt < 2; mt++) {
#pragma unroll
                    for (int hi = 0; hi < 2; hi++) {
                        const int row = m1 + mt * 16 + gid + hi * 8;
                        float vx = fmaxf(d1[mt][nt][hi * 2 + 0] + bv.x, 0.f);
                        float vy = fmaxf(d1[mt][nt][hi * 2 + 1] + bv.y, 0.f);
                        __half2 hv = __floats2half2_rn(vx, vy);
                        Hp[row * FH_U + (gn >> 1)] = *(uint32_t*)&hv;
                    }
                }
            }
        }
        __syncthreads();
    }

    // ================= phase 2: out = h @ W2^T + b2 + y ====================
    const int m2 = (wid >> 2) * 32;     // 0,32
    const int n2 = (wid & 3) * 64;      // 0,64,128,192

    auto issueB2 = [&](int c, int s) {
#pragma unroll
        for (int it = 0; it < 4; it++) {
            int fi  = tid + it * 256;
            int row = fi >> 2;
            int c4  = (fi & 3) * 4;
            cp_async16(B_u + (uint32_t)(s * FB_STG + row * LDU + c4) * 4,
                       W2 + (size_t)row * FFNDIM + c * 32 + c4 * 2);
        }
        cp_commit();
    };

    issueB2(0, 0);
    float d2[2][8][4];
#pragma unroll
    for (int mt = 0; mt < 2; mt++)
#pragma unroll
        for (int nt = 0; nt < 8; nt++)
#pragma unroll
            for (int j = 0; j < 4; j++) d2[mt][nt][j] = 0.0f;

    for (int c = 0; c < 32; c++) {
        if (c + 1 < 32) { issueB2(c + 1, (c + 1) & 1); cp_wait<1>(); }
        else            { cp_wait<0>(); }
        __syncthreads();

        const uint32_t Bb = B_u + (uint32_t)((c & 1) * FB_STG) * 4;

#pragma unroll
        for (int ks = 0; ks < 2; ks++) {
            const int ko = c * 16 + ks * 8;
            uint32_t a[2][4];
#pragma unroll
            for (int mt = 0; mt < 2; mt++) {
                uint32_t addr = H_u + (uint32_t)(
                    (m2 + mt * 16 + a_row) * FH_U + ko + a_kof) * 4;
                ldm_x4(a[mt][0], a[mt][1], a[mt][2], a[mt][3], addr);
            }
            uint32_t b[8][2];
#pragma unroll
            for (int np = 0; np < 4; np++) {
                uint32_t addr = Bb + (uint32_t)(
                    (n2 + np * 16 + b_row) * LDU + ks * 8 + b_kof) * 4;
                ldm_x4(b[2*np][0], b[2*np][1], b[2*np+1][0], b[2*np+1][1], addr);
            }
#pragma unroll
            for (int mt = 0; mt < 2; mt++)
#pragma unroll
                for (int nt = 0; nt < 8; nt++)
                    mma_f16(d2[mt][nt][0], d2[mt][nt][1], d2[mt][nt][2], d2[mt][nt][3],
                            a[mt][0], a[mt][1], a[mt][2], a[mt][3],
                            b[nt][0], b[nt][1]);
        }
        __syncthreads();
    }

    // epilogue: + b2 + y -> out (f32)
#pragma unroll
    for (int nt = 0; nt < 8; nt++) {
        const int n = n2 + nt * 8 + 2 * tg;
        const float2 bv = *(const float2*)&b2[n];
#pragma unroll
        for (int mt = 0; mt < 2; mt++) {
#pragma unroll
            for (int hi = 0; hi < 2; hi++) {
                const int m = bm + m2 + mt * 16 + gid + hi * 8;
                const __half2 r = *(const __half2*)&y[(size_t)m * DIM + n];
                float2 rf = __half22float2(r);
                float2 v;
                v.x = d2[mt][nt][hi * 2 + 0] + bv.x + rf.x;
                v.y = d2[mt][nt][hi * 2 + 1] + bv.y + rf.y;
                *(float2*)&out[(size_t)m * DIM + n] = v;
            }
        }
    }
}

// ===================== LayerNorm row helpers ================================
__device__ __forceinline__ void ln_row_f32(
    const float* __restrict__ x, const float* __restrict__ g,
    const float* __restrict__ b, __half* __restrict__ out,
    int row, int lane)
{
    const float4* xr = (const float4*)(x + (size_t)row * DIM);
    float4 v0 = xr[lane];
    float4 v1 = xr[lane + 32];

    float s = v0.x + v0.y + v0.z + v0.w + v1.x + v1.y + v1.z + v1.w;
    float q = v0.x*v0.x + v0.y*v0.y + v0.z*v0.z + v0.w*v0.w
            + v1.x*v1.x + v1.y*v1.y + v1.z*v1.z + v1.w*v1.w;
#pragma unroll
    for (int o = 16; o > 0; o >>= 1) {
        s += __shfl_xor_sync(0xffffffffu, s, o);
        q += __shfl_xor_sync(0xffffffffu, q, o);
    }
    float mean = s * (1.0f / 256.0f);
    float var  = q * (1.0f / 256.0f) - mean * mean;
    float inv  = rsqrtf(var + 1e-5f);

    const float4* g4 = (const float4*)g;
    const float4* b4 = (const float4*)b;
    float4 ga = g4[lane], gb = g4[lane + 32];
    float4 ba = b4[lane], bb = b4[lane + 32];

    __half2 h0 = __floats2half2_rn((v0.x - mean) * inv * ga.x + ba.x,
                                   (v0.y - mean) * inv * ga.y + ba.y);
    __half2 h1 = __floats2half2_rn((v0.z - mean) * inv * ga.z + ba.z,
                                   (v0.w - mean) * inv * ga.w + ba.w);
    __half2 h2 = __floats2half2_rn((v1.x - mean) * inv * gb.x + bb.x,
                                   (v1.y - mean) * inv * gb.y + bb.y);
    __half2 h3 = __floats2half2_rn((v1.z - mean) * inv * gb.z + bb.z,
                                   (v1.w - mean) * inv * gb.w + bb.w);

    __half* orow = out + (size_t)row * DIM;
    uint2 p0; p0.x = *(uint32_t*)&h0; p0.y = *(uint32_t*)&h1;
    uint2 p1; p1.x = *(uint32_t*)&h2; p1.y = *(uint32_t*)&h3;
    *(uint2*)(orow + lane * 4)       = p0;
    *(uint2*)(orow + 128 + lane * 4) = p1;
}

__device__ __forceinline__ void ln_row_f16(
    const __half* __restrict__ y, const float* __restrict__ g,
    const float* __restrict__ b, __half* __restrict__ out,
    int row, int lane)
{
    uint4 v = *(const uint4*)(y + (size_t)row * DIM + lane * 8);
    const __half2* vh = (const __half2*)&v;
    float f[8];
#pragma unroll
    for (int j = 0; j < 4; j++) {
        float2 ff = __half22float2(vh[j]);
        f[2*j] = ff.x; f[2*j + 1] = ff.y;
    }

    float s = 0.f, q = 0.f;
#pragma unroll
    for (int j = 0; j < 8; j++) { s += f[j]; q += f[j] * f[j]; }
#pragma unroll
    for (int o = 16; o > 0; o >>= 1) {
        s += __shfl_xor_sync(0xffffffffu, s, o);
        q += __shfl_xor_sync(0xffffffffu, q, o);
    }
    float mean = s * (1.0f / 256.0f);
    float var  = q * (1.0f / 256.0f) - mean * mean;
    float inv  = rsqrtf(var + 1e-5f);

    float4 ga = ((const float4*)g)[lane * 2];
    float4 gb = ((const float4*)g)[lane * 2 + 1];
    float4 ba = ((const float4*)b)[lane * 2];
    float4 bb = ((const float4*)b)[lane * 2 + 1];

    __half2 h0 = __floats2half2_rn((f[0] - mean) * inv * ga.x + ba.x,
                                   (f[1] - mean) * inv * ga.y + ba.y);
    __half2 h1 = __floats2half2_rn((f[2] - mean) * inv * ga.z + ba.z,
                                   (f[3] - mean) * inv * ga.w + ba.w);
    __half2 h2 = __floats2half2_rn((f[4] - mean) * inv * gb.x + bb.x,
                                   (f[5] - mean) * inv * gb.y + bb.y);
    __half2 h3 = __floats2half2_rn((f[6] - mean) * inv * gb.z + bb.z,
                                   (f[7] - mean) * inv * gb.w + bb.w);

    uint4 p;
    p.x = *(uint32_t*)&h0; p.y = *(uint32_t*)&h1;
    p.z = *(uint32_t*)&h2; p.w = *(uint32_t*)&h3;
    *(uint4*)(out + (size_t)row * DIM + lane * 8) = p;
}

// ===================== init: weight rounding + LN1, one launch ==============
__global__ void __launch_bounds__(256) init_kernel(
    const float* __restrict__ qkv_w, const float* __restrict__ proj_w,
    const float* __restrict__ ffn_w1, const float* __restrict__ ffn_w2,
    __half* __restrict__ wdst,
    const float* __restrict__ x, const float* __restrict__ ln1g,
    const float* __restrict__ ln1b, __half* __restrict__ xn)
{
    if (blockIdx.x < 768) {
        int i = blockIdx.x * 256 + threadIdx.x;      // float4 index
        const float* src;
        int local;
        if (i < 49152)       { src = qkv_w;  local = i;           }
        else if (i < 65536)  { src = proj_w; local = i - 49152;   }
        else if (i < 131072) { src = ffn_w1; local = i - 65536;   }
        else                 { src = ffn_w2; local = i - 131072;  }
        float4 v = ((const float4*)src)[local];
        __half2 lo = __floats2half2_rn(v.x, v.y);
        __half2 hi = __floats2half2_rn(v.z, v.w);
        uint2 o; o.x = *(uint32_t*)&lo; o.y = *(uint32_t*)&hi;
        ((uint2*)wdst)[i] = o;
    } else {
        int row = ((blockIdx.x - 768) * 256 + threadIdx.x) >> 5;
        ln_row_f32(x, ln1g, ln1b, xn, row, threadIdx.x & 31);
    }
}

// ===================== LayerNorm (LN2, half in/out) =========================
__global__ void __launch_bounds__(256) ln2_kernel(
    const __half* __restrict__ y, const float* __restrict__ g,
    const float* __restrict__ b, __half* __restrict__ out)
{
    int row = (blockIdx.x * blockDim.x + threadIdx.x) >> 5;
    ln_row_f16(y, g, b, out, row, threadIdx.x & 31);
}

// ===================== Per-token head-mixing attention ======================
__global__ void __launch_bounds__(256) attn_kernel(
    const __half* __restrict__ qkv, __half* __restrict__ out)
{
    const int idx = blockIdx.x * 256 + threadIdx.x;  // (token, head)
    const int t = idx >> 3;
    const int h = idx & 7;
    const __half* base = qkv + (size_t)t * 768;

    float q[HD];
#pragma unroll
    for (int c4 = 0; c4 < 4; c4++) {
        uint4 qv = *(const uint4*)(base + h * HD + c4 * 8);
        const __half2* qh = (const __half2*)&qv;
#pragma unroll
        for (int j = 0; j < 4; j++) {
            float2 f = __half22float2(qh[j]);
            q[c4 * 8 + 2*j] = f.x; q[c4 * 8 + 2*j + 1] = f.y;
        }
    }

    const float scale = 0.17677669529663688f;   // 1/sqrt(32)
    float sc[HEADS];
    float mx = -1e30f;
#pragma unroll
    for (int g = 0; g < HEADS; g++) {
        float s = 0.0f;
#pragma unroll
        for (int c4 = 0; c4 < 4; c4++) {
            uint4 kv = *(const uint4*)(base + 256 + g * HD + c4 * 8);
            const __half2* kh = (const __half2*)&kv;
#pragma unroll
            for (int j = 0; j < 4; j++) {
                float2 f = __half22float2(kh[j]);
                s += q[c4 * 8 + 2*j] * f.x + q[c4 * 8 + 2*j + 1] * f.y;
            }
        }
        s *= scale;
        sc[g] = s;
        mx = fmaxf(mx, s);
    }
    float sum = 0.0f;
#pragma unroll
    for (int g = 0; g < HEADS; g++) {
        float e = __expf(sc[g] - mx);
        sc[g] = e;
        sum += e;
    }
    const float inv = 1.0f / sum;

    float acc[HD];
#pragma unroll
    for (int d0 = 0; d0 < HD; d0++) acc[d0] = 0.0f;
#pragma unroll
    for (int g = 0; g < HEADS; g++) {
        const float p = sc[g];
#pragma unroll
        for (int c4 = 0; c4 < 4; c4++) {
            uint4 vv = *(const uint4*)(base + 512 + g * HD + c4 * 8);
            const __half2* vh = (const __half2*)&vv;
#pragma unroll
            for (int j = 0; j < 4; j++) {
                float2 f = __half22float2(vh[j]);
                acc[c4 * 8 + 2*j]     += p * f.x;
                acc[c4 * 8 + 2*j + 1] += p * f.y;
            }
        }
    }

    __half* orow = out + (size_t)t * DIM + h * HD;
#pragma unroll
    for (int c4 = 0; c4 < 4; c4++) {
        __half2 o0 = __floats2half2_rn(acc[c4*8+0] * inv, acc[c4*8+1] * inv);
        __half2 o1 = __floats2half2_rn(acc[c4*8+2] * inv, acc[c4*8+3] * inv);
        __half2 o2 = __floats2half2_rn(acc[c4*8+4] * inv, acc[c4*8+5] * inv);
        __half2 o3 = __floats2half2_rn(acc[c4*8+6] * inv, acc[c4*8+7] * inv);
        uint4 p;
        p.x = *(uint32_t*)&o0; p.y = *(uint32_t*)&o1;
        p.z = *(uint32_t*)&o2; p.w = *(uint32_t*)&o3;
        *(uint4*)(orow + c4 * 8) = p;
    }
}

// ===================== Launch ===============================================
extern "C" void kernel_launch(void* const* d_in, const int* in_sizes, int n_in,
                              void* d_out, int out_size)
{
    const float* x      = (const float*)d_in[0];
    const float* ln1_g  = (const float*)d_in[1];
    const float* ln1_b  = (const float*)d_in[2];
    const float* qkv_w  = (const float*)d_in[3];
    const float* qkv_b  = (const float*)d_in[4];
    const float* proj_w = (const float*)d_in[5];
    const float* proj_b = (const float*)d_in[6];
    const float* ln2_g  = (const float*)d_in[7];
    const float* ln2_b  = (const float*)d_in[8];
    const float* ffn_w1 = (const float*)d_in[9];
    const float* ffn_b1 = (const float*)d_in[10];
    const float* ffn_w2 = (const float*)d_in[11];
    const float* ffn_b2 = (const float*)d_in[12];

    __half *xn, *qkv, *attn, *y, *w;
    cudaGetSymbolAddress((void**)&xn,   g_xn);
    cudaGetSymbolAddress((void**)&qkv,  g_qkv);
    cudaGetSymbolAddress((void**)&attn, g_attn);
    cudaGetSymbolAddress((void**)&y,    g_y);
    cudaGetSymbolAddress((void**)&w,    g_w);
    float* out = (float*)d_out;

    cudaFuncSetAttribute(fused_ffn,
                         cudaFuncAttributeMaxDynamicSharedMemorySize, FUSED_SMEM);

    const int MROWS = TOKENS / TILE;   // 512

    // 0+1) weight rounding + LN1 in one launch
    init_kernel<<<768 + TOKENS / 8, 256>>>(
        qkv_w, proj_w, ffn_w1, ffn_w2, w, x, ln1_g, ln1_b, xn);
    // 2) QKV = xn @ qkv_w^T + qkv_b          [65536, 768] half
    mma_gemm<0, float, __half><<<dim3(768 / TILE, MROWS), 128>>>(
        xn, w + W_QKV, qkv_b, nullptr, qkv, DIM, 3 * DIM);
    // 3) per-token head-mixing attention (half out)
    attn_kernel<<<TOKENS * 8 / 256, 256>>>(qkv, attn);
    // 4) y = x + attn @ proj_w^T + proj_b    [65536, 256] half (res = x f32)
    mma_gemm<2, float, __half><<<dim3(DIM / TILE, MROWS), 128>>>(
        attn, w + W_PROJ, proj_b, x, y, DIM, DIM);
    // 5) LN2 (half in, half out)
    ln2_kernel<<<TOKENS / 8, 256>>>(y, ln2_g, ln2_b, xn);
    // 6+7) fused FFN: out = relu(xn@W1^T+b1)@W2^T + b2 + y   [65536, 256] f32
    fused_ffn<<<TOKENS / 64, 256, FUSED_SMEM>>>(
        xn, w + W_FFN1, ffn_b1, w + W_FFN2, ffn_b2, y, out);
}

// round 17
// speedup vs baseline: 1.2126x; 1.2126x over previous
#include <cuda_runtime.h>
#include <cuda_fp16.h>
#include <cstdint>

// ---------------------------------------------------------------------------
// SimpleMaxViTBlock: LN1 -> per-token head-mixing attention -> +res
//                    -> [LN2 folded into FFN1] -> FFN -> +res
// GEMMs: mma.sync m16n8k16 fp16, fp32 accum, ldmatrix, 4 warps (2x2) 64x64,
// double-buffered cp.async, 2 CTAs/SM (R8/R14 config - best measured).
// R17: LN2 folded algebraically into the FFN1 GEMM epilogue:
//   relu(ln2(y)@W1^T+b1) = relu(inv*(y@W1g^T) - inv*mean*S1 + S2)
// with W1g = W1*g, S1[n]=sum_k W1g[n,k], S2[n]=sum_k W1[n,k]*b[k]+b1[n].
// ln2_kernel becomes a stats-only kernel (0.5 MB out instead of 32 MB xn).
// ---------------------------------------------------------------------------

constexpr int TOKENS = 65536;
constexpr int DIM    = 256;
constexpr int HEADS  = 8;
constexpr int HD     = 32;
constexpr int FFNDIM = 1024;

// Scratch (device globals: allocation-free rule)
__device__ __half g_xn   [ (size_t)TOKENS * DIM    ];
__device__ __half g_qkv  [ (size_t)TOKENS * 3*DIM  ];
__device__ __half g_attn [ (size_t)TOKENS * DIM    ];
__device__ __half g_y    [ (size_t)TOKENS * DIM    ];   // fp16 residual
__device__ __half g_h    [ (size_t)TOKENS * FFNDIM ];
__device__ __half g_w    [ 786432 ];    // fp16 weights (FFN1 slot holds W1*g)
__device__ float  g_s1   [ FFNDIM ];    // sum_k W1g[n,k]
__device__ float  g_s2   [ FFNDIM ];    // sum_k W1[n,k]*b[k] + b1[n]
__device__ float2 g_stats[ TOKENS ];    // (mean, inv) per row of y

constexpr int W_QKV  = 0;
constexpr int W_PROJ = 196608;
constexpr int W_FFN1 = 262144;
constexpr int W_FFN2 = 524288;

// ===================== helpers ==============================================
__device__ __forceinline__ uint32_t smem_u32(const void* p) {
    uint32_t a;
    asm("{ .reg .u64 t; cvta.to.shared.u64 t, %1; cvt.u32.u64 %0, t; }"
        : "=r"(a) : "l"(p));
    return a;
}
__device__ __forceinline__ void cp_async16(uint32_t saddr, const void* gaddr) {
    asm volatile("cp.async.cg.shared.global [%0], [%1], 16;"
                 :: "r"(saddr), "l"(gaddr) : "memory");
}
__device__ __forceinline__ void cp_commit() {
    asm volatile("cp.async.commit_group;" ::: "memory");
}
template<int N>
__device__ __forceinline__ void cp_wait() {
    asm volatile("cp.async.wait_group %0;" :: "n"(N) : "memory");
}
__device__ __forceinline__ void ldm_x4(uint32_t& r0, uint32_t& r1,
                                       uint32_t& r2, uint32_t& r3, uint32_t addr) {
    asm volatile("ldmatrix.sync.aligned.m8n8.x4.shared.b16 {%0,%1,%2,%3}, [%4];"
                 : "=r"(r0), "=r"(r1), "=r"(r2), "=r"(r3) : "r"(addr));
}
__device__ __forceinline__ void mma_f16(
    float& d0, float& d1, float& d2, float& d3,
    uint32_t a0, uint32_t a1, uint32_t a2, uint32_t a3,
    uint32_t b0, uint32_t b1)
{
    asm volatile(
        "mma.sync.aligned.m16n8k16.row.col.f32.f16.f16.f32 "
        "{%0,%1,%2,%3}, {%4,%5,%6,%7}, {%8,%9}, {%0,%1,%2,%3};"
        : "+f"(d0), "+f"(d1), "+f"(d2), "+f"(d3)
        : "r"(a0), "r"(a1), "r"(a2), "r"(a3), "r"(b0), "r"(b1));
}

// ===================== fp16 mma.sync GEMM (R8/R14 config) ===================
// MODE: 0 = bias, 2 = bias+residual(ResT). (relu mode replaced by ffn1_ln.)
constexpr int TILE  = 128;
constexpr int BK    = 32;
constexpr int LDU   = 20;              // u32 per smem row (= 40 halves, 80B)
constexpr int SLABU = TILE * LDU;      // 2560 u32 per stage per matrix

template<int MODE, typename ResT, typename OutT>
__global__ void __launch_bounds__(128, 2) mma_gemm(
    const __half* __restrict__ A, const __half* __restrict__ B,
    const float* __restrict__ bias, const ResT* __restrict__ res,
    OutT* __restrict__ C, int K, int N)
{
    __shared__ __align__(16) uint32_t sm[4 * SLABU];   // 40960 B
    const uint32_t As_u = smem_u32(sm);
    const uint32_t Bs_u = As_u + 2 * SLABU * 4;

    const int tid  = threadIdx.x;
    const int wid  = tid >> 5;
    const int lane = tid & 31;
    const int gid  = lane >> 2;
    const int tg   = lane & 3;

    const int bm = blockIdx.y * TILE;
    const int bn = blockIdx.x * TILE;
    const int m_off = (wid >> 1) * 64;
    const int n_off = (wid & 1) * 64;

    const int lrow8 = lane & 7;
    const int a_row = (lrow8 + ((lane >> 3) & 1) * 8);
    const int a_kof = (lane >> 4) * 4;
    const int b_row = (lrow8 + ((lane >> 4) & 1) * 8);
    const int b_kof = ((lane >> 3) & 1) * 4;

    const int crow = tid >> 2;
    const int cc4  = (tid & 3) * 4;

    float d[4][8][4];
#pragma unroll
    for (int mt = 0; mt < 4; mt++)
#pragma unroll
        for (int nt = 0; nt < 8; nt++)
#pragma unroll
            for (int j = 0; j < 4; j++) d[mt][nt][j] = 0.0f;

    const int C_CHUNKS = K / BK;

    {
#pragma unroll
        for (int it = 0; it < 4; it++) {
            int row = crow + it * 32;
            cp_async16(As_u + (uint32_t)(row * LDU + cc4) * 4,
                       A + (size_t)(bm + row) * K + cc4 * 2);
            cp_async16(Bs_u + (uint32_t)(row * LDU + cc4) * 4,
                       B + (size_t)(bn + row) * K + cc4 * 2);
        }
        cp_commit();
    }

    for (int c = 0; c < C_CHUNKS; c++) {
        const int buf = c & 1;
        if (c + 1 < C_CHUNKS) {
            const int nb  = (c + 1) & 1;
            const int k0g = (c + 1) * BK;
#pragma unroll
            for (int it = 0; it < 4; it++) {
                int row = crow + it * 32;
                cp_async16(As_u + (uint32_t)((nb * SLABU + row * LDU + cc4) * 4),
                           A + (size_t)(bm + row) * K + k0g + cc4 * 2);
                cp_async16(Bs_u + (uint32_t)((nb * SLABU + row * LDU + cc4) * 4),
                           B + (size_t)(bn + row) * K + k0g + cc4 * 2);
            }
            cp_commit();
            cp_wait<1>();
        } else {
            cp_wait<0>();
        }
        __syncthreads();

        const uint32_t Ab = As_u + (uint32_t)(buf * SLABU) * 4;
        const uint32_t Bb = Bs_u + (uint32_t)(buf * SLABU) * 4;

#pragma unroll
        for (int ks = 0; ks < 2; ks++) {
            const int ko = ks * 8;
            uint32_t a[4][4];
#pragma unroll
            for (int mt = 0; mt < 4; mt++) {
                uint32_t addr = Ab + (uint32_t)(
                    (m_off + mt * 16 + a_row) * LDU + ko + a_kof) * 4;
                ldm_x4(a[mt][0], a[mt][1], a[mt][2], a[mt][3], addr);
            }
            uint32_t b[8][2];
#pragma unroll
            for (int np = 0; np < 4; np++) {
                uint32_t addr = Bb + (uint32_t)(
                    (n_off + np * 16 + b_row) * LDU + ko + b_kof) * 4;
                ldm_x4(b[2*np][0], b[2*np][1], b[2*np+1][0], b[2*np+1][1], addr);
            }
#pragma unroll
            for (int mt = 0; mt < 4; mt++)
#pragma unroll
                for (int nt = 0; nt < 8; nt++)
                    mma_f16(d[mt][nt][0], d[mt][nt][1], d[mt][nt][2], d[mt][nt][3],
                            a[mt][0], a[mt][1], a[mt][2], a[mt][3],
                            b[nt][0], b[nt][1]);
        }
        __syncthreads();
    }

#pragma unroll
    for (int nt = 0; nt < 8; nt++) {
        const int n = bn + n_off + nt * 8 + 2 * tg;
        const float2 bv = *(const float2*)&bias[n];
#pragma unroll
        for (int mt = 0; mt < 4; mt++) {
            const int m0 = bm + m_off + mt * 16 + gid;
#pragma unroll
            for (int half_i = 0; half_i < 2; half_i++) {
                const int m = m0 + half_i * 8;
                float vx = d[mt][nt][half_i * 2 + 0] + bv.x;
                float vy = d[mt][nt][half_i * 2 + 1] + bv.y;
                if (MODE == 2) {
                    if constexpr (sizeof(ResT) == 4) {
                        const float2 r = *(const float2*)&res[(size_t)m * N + n];
                        vx += r.x; vy += r.y;
                    } else {
                        const __half2 r = *(const __half2*)&res[(size_t)m * N + n];
                        float2 rf = __half22float2(r);
                        vx += rf.x; vy += rf.y;
                    }
                }
                if constexpr (sizeof(OutT) == 4) {
                    float2 v; v.x = vx; v.y = vy;
                    *(float2*)&((float*)C)[(size_t)m * N + n] = v;
                } else {
                    *(__half2*)&((__half*)C)[(size_t)m * N + n] =
                        __floats2half2_rn(vx, vy);
                }
            }
        }
    }
}

// ===================== FFN1 with folded LN2 =================================
// h = relu( inv_m * (y @ W1g^T) - inv_m*mean_m*S1[n] + S2[n] )
__global__ void __launch_bounds__(128, 2) ffn1_ln(
    const __half* __restrict__ A, const __half* __restrict__ B,
    const float2* __restrict__ stats, const float* __restrict__ S1,
    const float* __restrict__ S2, __half* __restrict__ C)
{
    const int K = DIM, N = FFNDIM;
    __shared__ __align__(16) uint32_t sm[4 * SLABU];
    const uint32_t As_u = smem_u32(sm);
    const uint32_t Bs_u = As_u + 2 * SLABU * 4;

    const int tid  = threadIdx.x;
    const int wid  = tid >> 5;
    const int lane = tid & 31;
    const int gid  = lane >> 2;
    const int tg   = lane & 3;

    const int bm = blockIdx.y * TILE;
    const int bn = blockIdx.x * TILE;
    const int m_off = (wid >> 1) * 64;
    const int n_off = (wid & 1) * 64;

    const int lrow8 = lane & 7;
    const int a_row = (lrow8 + ((lane >> 3) & 1) * 8);
    const int a_kof = (lane >> 4) * 4;
    const int b_row = (lrow8 + ((lane >> 4) & 1) * 8);
    const int b_kof = ((lane >> 3) & 1) * 4;

    const int crow = tid >> 2;
    const int cc4  = (tid & 3) * 4;

    float d[4][8][4];
#pragma unroll
    for (int mt = 0; mt < 4; mt++)
#pragma unroll
        for (int nt = 0; nt < 8; nt++)
#pragma unroll
            for (int j = 0; j < 4; j++) d[mt][nt][j] = 0.0f;

    {
#pragma unroll
        for (int it = 0; it < 4; it++) {
            int row = crow + it * 32;
            cp_async16(As_u + (uint32_t)(row * LDU + cc4) * 4,
                       A + (size_t)(bm + row) * K + cc4 * 2);
            cp_async16(Bs_u + (uint32_t)(row * LDU + cc4) * 4,
                       B + (size_t)(bn + row) * K + cc4 * 2);
        }
        cp_commit();
    }

    for (int c = 0; c < K / BK; c++) {
        const int buf = c & 1;
        if (c + 1 < K / BK) {
            const int nb  = (c + 1) & 1;
            const int k0g = (c + 1) * BK;
#pragma unroll
            for (int it = 0; it < 4; it++) {
                int row = crow + it * 32;
                cp_async16(As_u + (uint32_t)((nb * SLABU + row * LDU + cc4) * 4),
                           A + (size_t)(bm + row) * K + k0g + cc4 * 2);
                cp_async16(Bs_u + (uint32_t)((nb * SLABU + row * LDU + cc4) * 4),
                           B + (size_t)(bn + row) * K + k0g + cc4 * 2);
            }
            cp_commit();
            cp_wait<1>();
        } else {
            cp_wait<0>();
        }
        __syncthreads();

        const uint32_t Ab = As_u + (uint32_t)(buf * SLABU) * 4;
        const uint32_t Bb = Bs_u + (uint32_t)(buf * SLABU) * 4;

#pragma unroll
        for (int ks = 0; ks < 2; ks++) {
            const int ko = ks * 8;
            uint32_t a[4][4];
#pragma unroll
            for (int mt = 0; mt < 4; mt++) {
                uint32_t addr = Ab + (uint32_t)(
                    (m_off + mt * 16 + a_row) * LDU + ko + a_kof) * 4;
                ldm_x4(a[mt][0], a[mt][1], a[mt][2], a[mt][3], addr);
            }
            uint32_t b[8][2];
#pragma unroll
            for (int np = 0; np < 4; np++) {
                uint32_t addr = Bb + (uint32_t)(
                    (n_off + np * 16 + b_row) * LDU + ko + b_kof) * 4;
                ldm_x4(b[2*np][0], b[2*np][1], b[2*np+1][0], b[2*np+1][1], addr);
            }
#pragma unroll
            for (int mt = 0; mt < 4; mt++)
#pragma unroll
                for (int nt = 0; nt < 8; nt++)
                    mma_f16(d[mt][nt][0], d[mt][nt][1], d[mt][nt][2], d[mt][nt][3],
                            a[mt][0], a[mt][1], a[mt][2], a[mt][3],
                            b[nt][0], b[nt][1]);
        }
        __syncthreads();
    }

    // epilogue: folded LN2 + relu -> half
#pragma unroll
    for (int nt = 0; nt < 8; nt++) {
        const int n = bn + n_off + nt * 8 + 2 * tg;
        const float2 s1 = *(const float2*)&S1[n];
        const float2 s2 = *(const float2*)&S2[n];
#pragma unroll
        for (int mt = 0; mt < 4; mt++) {
            const int m0 = bm + m_off + mt * 16 + gid;
#pragma unroll
            for (int half_i = 0; half_i < 2; half_i++) {
                const int m = m0 + half_i * 8;
                const float2 st = stats[m];       // (mean, inv)
                const float corr = -st.y * st.x;  // -inv*mean
                float vx = fmaxf(st.y * d[mt][nt][half_i*2+0] + corr * s1.x + s2.x, 0.f);
                float vy = fmaxf(st.y * d[mt][nt][half_i*2+1] + corr * s1.y + s2.y, 0.f);
                *(__half2*)&C[(size_t)m * FFNDIM + n] = __floats2half2_rn(vx, vy);
            }
        }
    }
}

// ===================== LayerNorm row helper (LN1, f32 in) ===================
__device__ __forceinline__ void ln_row_f32(
    const float* __restrict__ x, const float* __restrict__ g,
    const float* __restrict__ b, __half* __restrict__ out,
    int row, int lane)
{
    const float4* xr = (const float4*)(x + (size_t)row * DIM);
    float4 v0 = xr[lane];
    float4 v1 = xr[lane + 32];

    float s = v0.x + v0.y + v0.z + v0.w + v1.x + v1.y + v1.z + v1.w;
    float q = v0.x*v0.x + v0.y*v0.y + v0.z*v0.z + v0.w*v0.w
            + v1.x*v1.x + v1.y*v1.y + v1.z*v1.z + v1.w*v1.w;
#pragma unroll
    for (int o = 16; o > 0; o >>= 1) {
        s += __shfl_xor_sync(0xffffffffu, s, o);
        q += __shfl_xor_sync(0xffffffffu, q, o);
    }
    float mean = s * (1.0f / 256.0f);
    float var  = q * (1.0f / 256.0f) - mean * mean;
    float inv  = rsqrtf(var + 1e-5f);

    const float4* g4 = (const float4*)g;
    const float4* b4 = (const float4*)b;
    float4 ga = g4[lane], gb = g4[lane + 32];
    float4 ba = b4[lane], bb = b4[lane + 32];

    __half2 h0 = __floats2half2_rn((v0.x - mean) * inv * ga.x + ba.x,
                                   (v0.y - mean) * inv * ga.y + ba.y);
    __half2 h1 = __floats2half2_rn((v0.z - mean) * inv * ga.z + ba.z,
                                   (v0.w - mean) * inv * ga.w + ba.w);
    __half2 h2 = __floats2half2_rn((v1.x - mean) * inv * gb.x + bb.x,
                                   (v1.y - mean) * inv * gb.y + bb.y);
    __half2 h3 = __floats2half2_rn((v1.z - mean) * inv * gb.z + bb.z,
                                   (v1.w - mean) * inv * gb.w + bb.w);

    __half* orow = out + (size_t)row * DIM;
    uint2 p0; p0.x = *(uint32_t*)&h0; p0.y = *(uint32_t*)&h1;
    uint2 p1; p1.x = *(uint32_t*)&h2; p1.y = *(uint32_t*)&h3;
    *(uint2*)(orow + lane * 4)       = p0;
    *(uint2*)(orow + 128 + lane * 4) = p1;
}

// ===================== init: weights (+W1*g), LN1, S1/S2 ====================
// blocks [0,768): round weights (FFN1 range multiplied by ln2_g first)
// blocks [768, 768+8192): LN1
// blocks [8960, 8964): S1/S2 per FFN1 output row
__global__ void __launch_bounds__(256) init_kernel(
    const float* __restrict__ qkv_w, const float* __restrict__ proj_w,
    const float* __restrict__ ffn_w1, const float* __restrict__ ffn_w2,
    __half* __restrict__ wdst,
    const float* __restrict__ x, const float* __restrict__ ln1g,
    const float* __restrict__ ln1b, __half* __restrict__ xn,
    const float* __restrict__ ln2g, const float* __restrict__ ln2b,
    const float* __restrict__ ffn_b1,
    float* __restrict__ S1, float* __restrict__ S2)
{
    const int bid = blockIdx.x;
    if (bid < 768) {
        int i = bid * 256 + threadIdx.x;             // float4 index
        const float* src;
        int local;
        bool isW1 = false;
        if (i < 49152)       { src = qkv_w;  local = i;           }
        else if (i < 65536)  { src = proj_w; local = i - 49152;   }
        else if (i < 131072) { src = ffn_w1; local = i - 65536; isW1 = true; }
        else                 { src = ffn_w2; local = i - 131072;  }
        float4 v = ((const float4*)src)[local];
        if (isW1) {
            float4 gv = ((const float4*)ln2g)[local & 63];  // k = (4*local)%256
            v.x *= gv.x; v.y *= gv.y; v.z *= gv.z; v.w *= gv.w;
        }
        __half2 lo = __floats2half2_rn(v.x, v.y);
        __half2 hi = __floats2half2_rn(v.z, v.w);
        uint2 o; o.x = *(uint32_t*)&lo; o.y = *(uint32_t*)&hi;
        ((uint2*)wdst)[i] = o;
    } else if (bid < 768 + 8192) {
        int row = ((bid - 768) * 256 + threadIdx.x) >> 5;
        ln_row_f32(x, ln1g, ln1b, xn, row, threadIdx.x & 31);
    } else {
        int n = (bid - 8960) * 256 + threadIdx.x;    // 0..1023
        const float4* wr = (const float4*)(ffn_w1 + (size_t)n * DIM);
        float s1 = 0.f, s2 = 0.f;
#pragma unroll 8
        for (int c4 = 0; c4 < 64; c4++) {
            float4 wv = wr[c4];
            float4 gv = ((const float4*)ln2g)[c4];
            float4 bv = ((const float4*)ln2b)[c4];
            s1 += wv.x*gv.x + wv.y*gv.y + wv.z*gv.z + wv.w*gv.w;
            s2 += wv.x*bv.x + wv.y*bv.y + wv.z*bv.z + wv.w*bv.w;
        }
        S1[n] = s1;
        S2[n] = s2 + ffn_b1[n];
    }
}

// ===================== LN2 stats kernel (y fp16 -> mean,inv) ================
__global__ void __launch_bounds__(256) stats_kernel(
    const __half* __restrict__ y, float2* __restrict__ stats)
{
    int row  = (blockIdx.x * blockDim.x + threadIdx.x) >> 5;
    int lane = threadIdx.x & 31;

    uint4 v = *(const uint4*)(y + (size_t)row * DIM + lane * 8);
    const __half2* vh = (const __half2*)&v;
    float s = 0.f, q = 0.f;
#pragma unroll
    for (int j = 0; j < 4; j++) {
        float2 f = __half22float2(vh[j]);
        s += f.x + f.y;
        q += f.x * f.x + f.y * f.y;
    }
#pragma unroll
    for (int o = 16; o > 0; o >>= 1) {
        s += __shfl_xor_sync(0xffffffffu, s, o);
        q += __shfl_xor_sync(0xffffffffu, q, o);
    }
    if (lane == 0) {
        float mean = s * (1.0f / 256.0f);
        float var  = q * (1.0f / 256.0f) - mean * mean;
        float2 st; st.x = mean; st.y = rsqrtf(var + 1e-5f);
        stats[row] = st;
    }
}

// ===================== Per-token head-mixing attention ======================
__global__ void __launch_bounds__(256) attn_kernel(
    const __half* __restrict__ qkv, __half* __restrict__ out)
{
    const int idx = blockIdx.x * 256 + threadIdx.x;  // (token, head)
    const int t = idx >> 3;
    const int h = idx & 7;
    const __half* base = qkv + (size_t)t * 768;

    float q[HD];
#pragma unroll
    for (int c4 = 0; c4 < 4; c4++) {
        uint4 qv = *(const uint4*)(base + h * HD + c4 * 8);
        const __half2* qh = (const __half2*)&qv;
#pragma unroll
        for (int j = 0; j < 4; j++) {
            float2 f = __half22float2(qh[j]);
            q[c4 * 8 + 2*j] = f.x; q[c4 * 8 + 2*j + 1] = f.y;
        }
    }

    const float scale = 0.17677669529663688f;   // 1/sqrt(32)
    float sc[HEADS];
    float mx = -1e30f;
#pragma unroll
    for (int g = 0; g < HEADS; g++) {
        float s = 0.0f;
#pragma unroll
        for (int c4 = 0; c4 < 4; c4++) {
            uint4 kv = *(const uint4*)(base + 256 + g * HD + c4 * 8);
            const __half2* kh = (const __half2*)&kv;
#pragma unroll
            for (int j = 0; j < 4; j++) {
                float2 f = __half22float2(kh[j]);
                s += q[c4 * 8 + 2*j] * f.x + q[c4 * 8 + 2*j + 1] * f.y;
            }
        }
        s *= scale;
        sc[g] = s;
        mx = fmaxf(mx, s);
    }
    float sum = 0.0f;
#pragma unroll
    for (int g = 0; g < HEADS; g++) {
        float e = __expf(sc[g] - mx);
        sc[g] = e;
        sum += e;
    }
    const float inv = 1.0f / sum;

    float acc[HD];
#pragma unroll
    for (int d0 = 0; d0 < HD; d0++) acc[d0] = 0.0f;
#pragma unroll
    for (int g = 0; g < HEADS; g++) {
        const float p = sc[g];
#pragma unroll
        for (int c4 = 0; c4 < 4; c4++) {
            uint4 vv = *(const uint4*)(base + 512 + g * HD + c4 * 8);
            const __half2* vh = (const __half2*)&vv;
#pragma unroll
            for (int j = 0; j < 4; j++) {
                float2 f = __half22float2(vh[j]);
                acc[c4 * 8 + 2*j]     += p * f.x;
                acc[c4 * 8 + 2*j + 1] += p * f.y;
            }
        }
    }

    __half* orow = out + (size_t)t * DIM + h * HD;
#pragma unroll
    for (int c4 = 0; c4 < 4; c4++) {
        __half2 o0 = __floats2half2_rn(acc[c4*8+0] * inv, acc[c4*8+1] * inv);
        __half2 o1 = __floats2half2_rn(acc[c4*8+2] * inv, acc[c4*8+3] * inv);
        __half2 o2 = __floats2half2_rn(acc[c4*8+4] * inv, acc[c4*8+5] * inv);
        __half2 o3 = __floats2half2_rn(acc[c4*8+6] * inv, acc[c4*8+7] * inv);
        uint4 p;
        p.x = *(uint32_t*)&o0; p.y = *(uint32_t*)&o1;
        p.z = *(uint32_t*)&o2; p.w = *(uint32_t*)&o3;
        *(uint4*)(orow + c4 * 8) = p;
    }
}

// ===================== Launch ===============================================
extern "C" void kernel_launch(void* const* d_in, const int* in_sizes, int n_in,
                              void* d_out, int out_size)
{
    const float* x      = (const float*)d_in[0];
    const float* ln1_g  = (const float*)d_in[1];
    const float* ln1_b  = (const float*)d_in[2];
    const float* qkv_w  = (const float*)d_in[3];
    const float* qkv_b  = (const float*)d_in[4];
    const float* proj_w = (const float*)d_in[5];
    const float* proj_b = (const float*)d_in[6];
    const float* ln2_g  = (const float*)d_in[7];
    const float* ln2_b  = (const float*)d_in[8];
    const float* ffn_w1 = (const float*)d_in[9];
    const float* ffn_b1 = (const float*)d_in[10];
    const float* ffn_w2 = (const float*)d_in[11];
    const float* ffn_b2 = (const float*)d_in[12];

    __half *xn, *qkv, *attn, *y, *h, *w;
    float *s1, *s2;
    float2 *stats;
    cudaGetSymbolAddress((void**)&xn,    g_xn);
    cudaGetSymbolAddress((void**)&qkv,   g_qkv);
    cudaGetSymbolAddress((void**)&attn,  g_attn);
    cudaGetSymbolAddress((void**)&y,     g_y);
    cudaGetSymbolAddress((void**)&h,     g_h);
    cudaGetSymbolAddress((void**)&w,     g_w);
    cudaGetSymbolAddress((void**)&s1,    g_s1);
    cudaGetSymbolAddress((void**)&s2,    g_s2);
    cudaGetSymbolAddress((void**)&stats, g_stats);
    float* out = (float*)d_out;

    const int MROWS = TOKENS / TILE;   // 512

    // 0+1) weight rounding (+W1*g) + LN1 + S1/S2 in one launch
    init_kernel<<<768 + TOKENS / 8 + 4, 256>>>(
        qkv_w, proj_w, ffn_w1, ffn_w2, w, x, ln1_g, ln1_b, xn,
        ln2_g, ln2_b, ffn_b1, s1, s2);
    // 2) QKV = xn @ qkv_w^T + qkv_b          [65536, 768] half
    mma_gemm<0, float, __half><<<dim3(768 / TILE, MROWS), 128>>>(
        xn, w + W_QKV, qkv_b, nullptr, qkv, DIM, 3 * DIM);
    // 3) per-token head-mixing attention (half out)
    attn_kernel<<<TOKENS * 8 / 256, 256>>>(qkv, attn);
    // 4) y = x + attn @ proj_w^T + proj_b    [65536, 256] half (res = x f32)
    mma_gemm<2, float, __half><<<dim3(DIM / TILE, MROWS), 128>>>(
        attn, w + W_PROJ, proj_b, x, y, DIM, DIM);
    // 5) LN2 stats only (mean, inv per row of y)
    stats_kernel<<<TOKENS / 8, 256>>>(y, stats);
    // 6) h = relu(inv*(y@W1g^T) - inv*mean*S1 + S2)   [65536, 1024] half
    ffn1_ln<<<dim3(FFNDIM / TILE, MROWS), 128>>>(
        y, w + W_FFN1, stats, s1, s2, h);
    // 7) out = y + h @ ffn_w2^T + ffn_b2     [65536, 256] f32 (res = y half)
    mma_gemm<2, __half, float><<<dim3(DIM / TILE, MROWS), 128>>>(
        h, w + W_FFN2, ffn_b2, y, out, FFNDIM, DIM);
}